// round 4
// baseline (speedup 1.0000x reference)
#include <cuda_runtime.h>
#include <cstddef>

#define Bn  4
#define NHn 8
#define Cn  32
#define Hn  128
#define Wn  128
#define HWn (Hn*Wn)
#define CDn 256

typedef unsigned long long ull;

// ---------------- scratch (device globals; no allocation allowed) ----------------
__device__ __align__(16) float g_qp [Bn*HWn*Cn];           // NHWC
__device__ __align__(16) float g_pc [Bn*HWn*Cn];           // NHWC
__device__ __align__(16) float g_xi [Bn*NHn*HWn*Cn];       // per-image NHWC (img = b*8+n)
__device__ __align__(16) float g_cat[(size_t)Bn*NHn*HWn*96]; // per-image NHWC-96: [x112|x223|x33]

__device__ __align__(16) float g_w1 [NHn*9*Cn*96];   // [h][tap][ci][co]  scale-folded
__device__ __align__(16) float g_b1 [NHn*96];
__device__ __align__(16) float g_w2 [NHn*9*Cn*64];
__device__ __align__(16) float g_b2 [NHn*64];
__device__ __align__(16) float g_w3k[NHn*9*Cn*32];
__device__ __align__(16) float g_b3k[NHn*32];
__device__ __align__(16) float g_wc [NHn*96*32];     // [h][cin][co]      scale-folded
__device__ __align__(16) float g_bc [NHn*32];
__device__ __align__(16) float g_wv [CDn*Cn];        // [ci][co]          scale-folded
__device__ __align__(16) float g_wvb[Cn];

// ---------------- helpers ----------------
__device__ __forceinline__ float4 f4fma(float a, float4 w, float4 acc) {
    acc.x = fmaf(a, w.x, acc.x); acc.y = fmaf(a, w.y, acc.y);
    acc.z = fmaf(a, w.z, acc.z); acc.w = fmaf(a, w.w, acc.w);
    return acc;
}
__device__ __forceinline__ float4 add4(float4 a, float4 b) {
    return make_float4(a.x+b.x, a.y+b.y, a.z+b.z, a.w+b.w);
}
__device__ __forceinline__ float4 relu6_4(float4 v) {
    v.x = fminf(fmaxf(v.x, 0.f), 6.f); v.y = fminf(fmaxf(v.y, 0.f), 6.f);
    v.z = fminf(fmaxf(v.z, 0.f), 6.f); v.w = fminf(fmaxf(v.w, 0.f), 6.f);
    return v;
}

// packed fp32x2 FMA (SASS FFMA2 — only reachable via PTX)
__device__ __forceinline__ ull ffma2(ull a, ull b, ull c) {
    ull d;
    asm("fma.rn.f32x2 %0, %1, %2, %3;" : "=l"(d) : "l"(a), "l"(b), "l"(c));
    return d;
}
__device__ __forceinline__ ull bcast2(float x) {
    ull r;
    asm("mov.b64 %0, {%1, %1};" : "=l"(r) : "f"(x));
    return r;
}
__device__ __forceinline__ float4 uns2f4(ull lo, ull hi) {
    union { ull u; float2 f; } a, b;
    a.u = lo; b.u = hi;
    return make_float4(a.f.x, a.f.y, b.f.x, b.f.y);
}

// ---------------- weight prep: fold BN scales, reorder to [tap][ci][co] ----------------
__global__ void prep_kernel(const float* __restrict__ wv_w, const float* __restrict__ wv_s,
                            const float* __restrict__ wv_b, const float* __restrict__ w3,
                            const float* __restrict__ s3,   const float* __restrict__ b3,
                            const float* __restrict__ wcat, const float* __restrict__ scat,
                            const float* __restrict__ bcat)
{
    int t = blockIdx.x * blockDim.x + threadIdx.x;
    const int N1 = NHn*9*Cn*96, N2 = NHn*9*Cn*64, N3 = NHn*9*Cn*32;
    const int NC = NHn*96*Cn,   NV = CDn*Cn;
    if (t < N1) {
        int co = t % 96; int r = t / 96; int ci = r % 32; r /= 32; int tap = r % 9; int h = r / 9;
        int j = co >> 5, oc = co & 31, ky = tap / 3, kx = tap % 3;
        g_w1[t] = w3[((((h*6 + j)*32 + oc)*32 + ci)*3 + ky)*3 + kx] * s3[(h*6 + j)*32 + oc];
        return;
    } t -= N1;
    if (t < N2) {
        int co = t % 64; int r = t / 64; int ci = r % 32; r /= 32; int tap = r % 9; int h = r / 9;
        int j = 3 + (co >> 5), oc = co & 31, ky = tap / 3, kx = tap % 3;
        g_w2[t] = w3[((((h*6 + j)*32 + oc)*32 + ci)*3 + ky)*3 + kx] * s3[(h*6 + j)*32 + oc];
        return;
    } t -= N2;
    if (t < N3) {
        int co = t % 32; int r = t / 32; int ci = r % 32; r /= 32; int tap = r % 9; int h = r / 9;
        int oc = co, ky = tap / 3, kx = tap % 3;
        g_w3k[t] = w3[((((h*6 + 5)*32 + oc)*32 + ci)*3 + ky)*3 + kx] * s3[(h*6 + 5)*32 + oc];
        return;
    } t -= N3;
    if (t < NC) {
        int co = t & 31; int r = t >> 5; int ci = r % 96; int h = r / 96;
        g_wc[t] = wcat[(h*32 + co)*96 + ci] * scat[h*32 + co];
        return;
    } t -= NC;
    if (t < NV) {
        int co = t & 31; int ci = t >> 5;
        g_wv[t] = wv_w[co*CDn + ci] * wv_s[co];
        return;
    } t -= NV;
    if (t < NHn*96) {
        int co = t % 96; int h = t / 96; int j = co >> 5, oc = co & 31;
        g_b1[t] = b3[(h*6 + j)*32 + oc]; return;
    } t -= NHn*96;
    if (t < NHn*64) {
        int co = t % 64; int h = t / 64; int j = 3 + (co >> 5), oc = co & 31;
        g_b2[t] = b3[(h*6 + j)*32 + oc]; return;
    } t -= NHn*64;
    if (t < NHn*32) {
        int oc = t & 31; int h = t >> 5;
        g_b3k[t] = b3[(h*6 + 5)*32 + oc]; return;
    } t -= NHn*32;
    if (t < NHn*32) { g_bc[t] = bcat[t]; return; }
    t -= NHn*32;
    if (t < Cn) { g_wvb[t] = wv_b[t]; }
}

// ---------------- qp = relu(conv1x1(res) + bias), NCHW -> NHWC  (f32x2) ----------------
__global__ void __launch_bounds__(128) qp_kernel(const float* __restrict__ res)
{
    __shared__ __align__(16) float sw[CDn*Cn];
    __shared__ float sb[Cn];
    for (int i = threadIdx.x; i < CDn*Cn; i += 128) sw[i] = g_wv[i];
    if (threadIdx.x < Cn) sb[threadIdx.x] = g_wvb[threadIdx.x];
    __syncthreads();

    int p0 = blockIdx.x * 256 + threadIdx.x;       // 256-px blocks never straddle batch
    int b  = p0 >> 14;  int pix0 = p0 & 16383;
    const float* r0 = res + (size_t)b * CDn * HWn + pix0;

    ull a0[16], a1[16];
    #pragma unroll
    for (int j = 0; j < 16; j++) { a0[j] = 0ull; a1[j] = 0ull; }

    #pragma unroll 1
    for (int ci = 0; ci < CDn; ci++) {
        ull x0 = bcast2(r0[(size_t)ci * HWn]);
        ull x1 = bcast2(r0[(size_t)ci * HWn + 128]);
        const ulonglong2* wr = (const ulonglong2*)(sw + ci*Cn);
        #pragma unroll
        for (int j = 0; j < 8; j++) {
            ulonglong2 w = wr[j];
            a0[2*j]   = ffma2(x0, w.x, a0[2*j]);
            a0[2*j+1] = ffma2(x0, w.y, a0[2*j+1]);
            a1[2*j]   = ffma2(x1, w.x, a1[2*j]);
            a1[2*j+1] = ffma2(x1, w.y, a1[2*j+1]);
        }
    }
    float4* o0 = (float4*)(g_qp + (size_t)p0 * Cn);
    float4* o1 = (float4*)(g_qp + (size_t)(p0 + 128) * Cn);
    #pragma unroll
    for (int j = 0; j < 8; j++) {
        float4 v0 = uns2f4(a0[2*j], a0[2*j+1]);
        float4 v1 = uns2f4(a1[2*j], a1[2*j+1]);
        v0.x = fmaxf(v0.x + sb[j*4+0], 0.f); v0.y = fmaxf(v0.y + sb[j*4+1], 0.f);
        v0.z = fmaxf(v0.z + sb[j*4+2], 0.f); v0.w = fmaxf(v0.w + sb[j*4+3], 0.f);
        v1.x = fmaxf(v1.x + sb[j*4+0], 0.f); v1.y = fmaxf(v1.y + sb[j*4+1], 0.f);
        v1.z = fmaxf(v1.z + sb[j*4+2], 0.f); v1.w = fmaxf(v1.w + sb[j*4+3], 0.f);
        o0[j] = v0; o1[j] = v1;
    }
}

// ---------------- point attention: dilated 5x5 window, stride 2 ----------------
__global__ void __launch_bounds__(256) pa_kernel()
{
    int p = blockIdx.x * 256 + threadIdx.x;
    int b = p >> 14, pix = p & 16383, h = pix >> 7, w = pix & 127;

    const float4* q4 = (const float4*)g_qp + (size_t)p * 8;
    float4 q[8];
    #pragma unroll
    for (int j = 0; j < 8; j++) q[j] = q4[j];

    float sc[25];
    #pragma unroll
    for (int k = 0; k < 25; k++) {
        int di = (k / 5) * 2 - 4, dj = (k % 5) * 2 - 4;
        int hh = h + di, ww = w + dj;
        float s = 0.f;
        if (k != 12 && hh >= 0 && hh < Hn && ww >= 0 && ww < Wn) {
            const float4* nb = (const float4*)g_qp + (size_t)((b << 14) + (hh << 7) + ww) * 8;
            #pragma unroll
            for (int j = 0; j < 8; j++) {
                float4 v = nb[j];
                s += q[j].x*v.x + q[j].y*v.y + q[j].z*v.z + q[j].w*v.w;
            }
        }
        sc[k] = s;
    }
    float m = sc[0];
    #pragma unroll
    for (int k = 1; k < 25; k++) m = fmaxf(m, sc[k]);
    float Z = 0.f;
    #pragma unroll
    for (int k = 0; k < 25; k++) { sc[k] = __expf(sc[k] - m); Z += sc[k]; }
    float inv = 1.f / Z;

    float4 acc[8];
    #pragma unroll
    for (int j = 0; j < 8; j++) acc[j] = q[j];   // pc = qp + sum_k pa_k * q25_k
    #pragma unroll
    for (int k = 0; k < 25; k++) {
        int di = (k / 5) * 2 - 4, dj = (k % 5) * 2 - 4;
        int hh = h + di, ww = w + dj;
        if (hh >= 0 && hh < Hn && ww >= 0 && ww < Wn) {
            float wgt = sc[k] * inv;
            const float4* nb = (const float4*)g_qp + (size_t)((b << 14) + (hh << 7) + ww) * 8;
            #pragma unroll
            for (int j = 0; j < 8; j++) acc[j] = f4fma(wgt, nb[j], acc[j]);
        }
    }
    float4* o = (float4*)(g_pc + (size_t)p * Cn);
    #pragma unroll
    for (int j = 0; j < 8; j++) o[j] = acc[j];
}

// ---------------- class attention + per-head norm + residual -> xi ----------------
__global__ void __launch_bounds__(256) ca_kernel(const float* __restrict__ attn,
                                                 const float* __restrict__ cn_s,
                                                 const float* __restrict__ cn_b)
{
    int p = blockIdx.x * 256 + threadIdx.x;
    int b = p >> 14, pix = p & 16383;

    float pcf[32];
    const float4* pc4 = (const float4*)g_pc + (size_t)p * 8;
    #pragma unroll
    for (int j = 0; j < 8; j++) {
        float4 v = pc4[j];
        pcf[j*4+0] = v.x; pcf[j*4+1] = v.y; pcf[j*4+2] = v.z; pcf[j*4+3] = v.w;
    }
    float s[8];
    #pragma unroll
    for (int n = 0; n < 8; n++) {
        const float* ap = attn + ((size_t)b * CDn + n * Cn) * HWn + pix;
        float acc = 0.f;
        #pragma unroll
        for (int c = 0; c < 32; c++) acc += pcf[c] * ap[(size_t)c * HWn];
        s[n] = acc;
    }
    float m = s[0];
    #pragma unroll
    for (int n = 1; n < 8; n++) m = fmaxf(m, s[n]);
    float Z = 0.f;
    #pragma unroll
    for (int n = 0; n < 8; n++) { s[n] = __expf(s[n] - m); Z += s[n]; }
    float inv = 1.f / Z;

    #pragma unroll
    for (int n = 0; n < 8; n++) {
        float wn = s[n] * inv;
        const float* ap = attn + ((size_t)b * CDn + n * Cn) * HWn + pix;
        float4* xo = (float4*)(g_xi + ((size_t)(b * NHn + n) * HWn + pix) * Cn);
        #pragma unroll
        for (int c4 = 0; c4 < 8; c4++) {
            float4 o;
            int c = c4 * 4;
            o.x = ap[(size_t)(c+0)*HWn] + wn * pcf[c+0] * __ldg(&cn_s[n*32+c+0]) + __ldg(&cn_b[n*32+c+0]);
            o.y = ap[(size_t)(c+1)*HWn] + wn * pcf[c+1] * __ldg(&cn_s[n*32+c+1]) + __ldg(&cn_b[n*32+c+1]);
            o.z = ap[(size_t)(c+2)*HWn] + wn * pcf[c+2] * __ldg(&cn_s[n*32+c+2]) + __ldg(&cn_b[n*32+c+2]);
            o.w = ap[(size_t)(c+3)*HWn] + wn * pcf[c+3] * __ldg(&cn_s[n*32+c+3]) + __ldg(&cn_b[n*32+c+3]);
            xo[c4] = o;
        }
    }
}

// ---------------- fused MSConv 3x3 stage (f32x2): conv 32->NOUT, BN(relu6), group-sum ----------------
// S=1: g_xi(32ch)  -> 96-wide -> sum3 -> cat[0:32)
// S=2: cat[0:32)   -> 64-wide -> sum2 -> cat[32:64)
// S=3: cat[32:64)  -> 32-wide        -> cat[64:96)
template <int S>
__global__ void __launch_bounds__(256, 1) conv3x3_kernel()
{
    constexpr int NOUT = (S == 1) ? 96 : (S == 2) ? 64 : 32;
    constexpr int NSUM = (S == 1) ? 3  : (S == 2) ? 2  : 1;
    constexpr int INS  = (S == 1) ? 32 : 96;
    constexpr int INOFF  = (S == 3) ? 32 : 0;
    constexpr int OUTOFF = (S == 1) ? 0 : (S == 2) ? 32 : 64;
    constexpr int NJ = NOUT / 4;      // float4 groups of output channels
    constexpr int NA = NOUT / 2;      // f32x2 accumulators

    extern __shared__ float smem[];
    float4*       sX  = (float4*)smem;                       // 8 planes of 18x18 float4
    float4*       sW  = (float4*)(smem + 2592 * 4);          // [tap][ci][co/4]
    const float4* sB4 = (const float4*)(smem + 2592 * 4 + 9 * 32 * NOUT);

    const int img  = blockIdx.y;          // b*8 + n
    const int head = img & 7;
    const int ty0 = (blockIdx.x >> 3) * 16, tx0 = (blockIdx.x & 7) * 16;
    const int tid = threadIdx.x;

    const float* in = (S == 1) ? g_xi : g_cat;
    const float* Wt = (S == 1) ? g_w1 : (S == 2) ? g_w2 : g_w3k;
    const float* Bs = (S == 1) ? g_b1 : (S == 2) ? g_b2 : g_b3k;

    const float4* gw = (const float4*)(Wt + (size_t)head * 9 * 32 * NOUT);
    const int NW = 9 * 32 * NOUT / 4;
    for (int i = tid; i < NW; i += 256) sW[i] = gw[i];
    {
        float* sBf = smem + 2592 * 4 + 9 * 32 * NOUT;
        for (int i = tid; i < NOUT; i += 256) sBf[i] = Bs[head * NOUT + i];
    }
    const float* gin = in + (size_t)img * HWn * INS + INOFF;
    for (int e = tid; e < 2592; e += 256) {
        int c4 = e & 7, pix = e >> 3;
        int iy = pix / 18, ix = pix - iy * 18;
        int hh = ty0 - 1 + iy, ww = tx0 - 1 + ix;
        float4 v = make_float4(0, 0, 0, 0);
        if (hh >= 0 && hh < Hn && ww >= 0 && ww < Wn)
            v = *(const float4*)(gin + (size_t)(hh * Wn + ww) * INS + c4 * 4);
        sX[c4 * 324 + pix] = v;
    }
    __syncthreads();

    const int px = tid & 15, py = tid >> 4;
    ull acc[NA];
    #pragma unroll
    for (int j = 0; j < NA; j++) acc[j] = 0ull;

    #pragma unroll 1
    for (int tap = 0; tap < 9; tap++) {
        const int ky = tap / 3, kx = tap - ky * 3;
        const float4* xrow = sX + (py + ky) * 18 + (px + kx);
        const ulonglong2* wt = (const ulonglong2*)(sW + tap * (32 * NJ));
        #pragma unroll 1
        for (int c4 = 0; c4 < 8; c4++) {
            float4 xv = xrow[c4 * 324];
            ull xs0 = bcast2(xv.x), xs1 = bcast2(xv.y);
            ull xs2 = bcast2(xv.z), xs3 = bcast2(xv.w);
            const ulonglong2* w0 = wt + (c4 * 4) * NJ;
            #pragma unroll
            for (int j = 0; j < NJ; j++) {
                ulonglong2 wa = w0[j];
                acc[2*j]   = ffma2(xs0, wa.x, acc[2*j]);
                acc[2*j+1] = ffma2(xs0, wa.y, acc[2*j+1]);
            }
            #pragma unroll
            for (int j = 0; j < NJ; j++) {
                ulonglong2 wb = w0[NJ + j];
                acc[2*j]   = ffma2(xs1, wb.x, acc[2*j]);
                acc[2*j+1] = ffma2(xs1, wb.y, acc[2*j+1]);
            }
            #pragma unroll
            for (int j = 0; j < NJ; j++) {
                ulonglong2 wc2 = w0[2*NJ + j];
                acc[2*j]   = ffma2(xs2, wc2.x, acc[2*j]);
                acc[2*j+1] = ffma2(xs2, wc2.y, acc[2*j+1]);
            }
            #pragma unroll
            for (int j = 0; j < NJ; j++) {
                ulonglong2 wd = w0[3*NJ + j];
                acc[2*j]   = ffma2(xs3, wd.x, acc[2*j]);
                acc[2*j+1] = ffma2(xs3, wd.y, acc[2*j+1]);
            }
        }
    }

    float* gout = g_cat + ((size_t)img * HWn + (ty0 + py) * Wn + (tx0 + px)) * 96 + OUTOFF;
    #pragma unroll
    for (int j = 0; j < 8; j++) {
        float4 sum = relu6_4(add4(uns2f4(acc[2*j], acc[2*j+1]), sB4[j]));
        if (NSUM > 1) sum = add4(sum, relu6_4(add4(uns2f4(acc[16 + 2*j], acc[16 + 2*j+1]), sB4[8 + j])));
        if (NSUM > 2) sum = add4(sum, relu6_4(add4(uns2f4(acc[32 + 2*j], acc[32 + 2*j+1]), sB4[16 + j])));
        *(float4*)(gout + j * 4) = sum;
    }
}

// ---------------- 1x1 conv 96->32 + bias + residual(xi) + relu -> NCHW out (f32x2) ----------------
__global__ void __launch_bounds__(256) final_kernel(float* __restrict__ out)
{
    __shared__ __align__(16) float sw[96 * 32];
    __shared__ float sb[32];
    const int img = blockIdx.y, head = img & 7;
    const float* gw = g_wc + (size_t)head * 96 * 32;
    for (int i = threadIdx.x; i < 96 * 32; i += 256) sw[i] = gw[i];
    if (threadIdx.x < 32) sb[threadIdx.x] = g_bc[head * 32 + threadIdx.x];
    __syncthreads();

    const int p = blockIdx.x * 256 + threadIdx.x;   // pixel in image
    const float4* cv = (const float4*)(g_cat + ((size_t)img * HWn + p) * 96);

    ull acc[16];
    #pragma unroll
    for (int j = 0; j < 16; j++) acc[j] = 0ull;

    #pragma unroll 1
    for (int ci4 = 0; ci4 < 24; ci4++) {
        float4 x = cv[ci4];
        ull x0 = bcast2(x.x), x1 = bcast2(x.y), x2 = bcast2(x.z), x3 = bcast2(x.w);
        const ulonglong2* w0 = (const ulonglong2*)(sw + (ci4 * 4 + 0) * 32);
        const ulonglong2* w1 = (const ulonglong2*)(sw + (ci4 * 4 + 1) * 32);
        const ulonglong2* w2 = (const ulonglong2*)(sw + (ci4 * 4 + 2) * 32);
        const ulonglong2* w3p = (const ulonglong2*)(sw + (ci4 * 4 + 3) * 32);
        #pragma unroll
        for (int j = 0; j < 8; j++) {
            ulonglong2 wa = w0[j];
            acc[2*j]   = ffma2(x0, wa.x, acc[2*j]);
            acc[2*j+1] = ffma2(x0, wa.y, acc[2*j+1]);
            ulonglong2 wb = w1[j];
            acc[2*j]   = ffma2(x1, wb.x, acc[2*j]);
            acc[2*j+1] = ffma2(x1, wb.y, acc[2*j+1]);
            ulonglong2 wc2 = w2[j];
            acc[2*j]   = ffma2(x2, wc2.x, acc[2*j]);
            acc[2*j+1] = ffma2(x2, wc2.y, acc[2*j+1]);
            ulonglong2 wd = w3p[j];
            acc[2*j]   = ffma2(x3, wd.x, acc[2*j]);
            acc[2*j+1] = ffma2(x3, wd.y, acc[2*j+1]);
        }
    }
    const float4* xiv = (const float4*)(g_xi + ((size_t)img * HWn + p) * Cn);
    #pragma unroll
    for (int j = 0; j < 8; j++) {
        float4 av = uns2f4(acc[2*j], acc[2*j+1]);
        float4 xr = xiv[j];
        float ox = fmaxf(av.x + sb[j*4+0] + xr.x, 0.f);
        float oy = fmaxf(av.y + sb[j*4+1] + xr.y, 0.f);
        float oz = fmaxf(av.z + sb[j*4+2] + xr.z, 0.f);
        float ow = fmaxf(av.w + sb[j*4+3] + xr.w, 0.f);
        size_t base = (size_t)(img * 32 + j * 4) * HWn + p;
        out[base]           = ox;
        out[base + HWn]     = oy;
        out[base + 2*HWn]   = oz;
        out[base + 3*HWn]   = ow;
    }
}

// ---------------- launch ----------------
extern "C" void kernel_launch(void* const* d_in, const int* in_sizes, int n_in,
                              void* d_out, int out_size)
{
    (void)in_sizes; (void)n_in; (void)out_size;
    const float* res  = (const float*)d_in[0];
    const float* attn = (const float*)d_in[1];
    const float* wv_w = (const float*)d_in[2];
    const float* wv_s = (const float*)d_in[3];
    const float* wv_b = (const float*)d_in[4];
    const float* cn_s = (const float*)d_in[5];
    const float* cn_b = (const float*)d_in[6];
    const float* w3   = (const float*)d_in[7];
    const float* s3   = (const float*)d_in[8];
    const float* b3   = (const float*)d_in[9];
    const float* wcat = (const float*)d_in[10];
    const float* scat = (const float*)d_in[11];
    const float* bcat = (const float*)d_in[12];
    float* out = (float*)d_out;

    const int smem1 = (2592 * 4 + 9 * 32 * 96 + 96) * 4;   // 152448
    const int smem2 = (2592 * 4 + 9 * 32 * 64 + 64) * 4;   // 115456
    const int smem3 = (2592 * 4 + 9 * 32 * 32 + 32) * 4;   //  78464
    cudaFuncSetAttribute(conv3x3_kernel<1>, cudaFuncAttributeMaxDynamicSharedMemorySize, smem1);
    cudaFuncSetAttribute(conv3x3_kernel<2>, cudaFuncAttributeMaxDynamicSharedMemorySize, smem2);
    cudaFuncSetAttribute(conv3x3_kernel<3>, cudaFuncAttributeMaxDynamicSharedMemorySize, smem3);

    prep_kernel<<<1864, 256>>>(wv_w, wv_s, wv_b, w3, s3, b3, wcat, scat, bcat);
    qp_kernel<<<256, 128>>>(res);
    pa_kernel<<<256, 256>>>();
    ca_kernel<<<256, 256>>>(attn, cn_s, cn_b);
    conv3x3_kernel<1><<<dim3(64, 32), 256, smem1>>>();
    conv3x3_kernel<2><<<dim3(64, 32), 256, smem2>>>();
    conv3x3_kernel<3><<<dim3(64, 32), 256, smem3>>>();
    final_kernel<<<dim3(64, 32), 256>>>(out);
}

// round 6
// speedup vs baseline: 3.4996x; 3.4996x over previous
#include <cuda_runtime.h>
#include <cuda_bf16.h>
#include <cstdint>
#include <cstddef>

#define Bn  4
#define NHn 8
#define Cn  32
#define Hn  128
#define Wn  128
#define HWn (Hn*Wn)
#define CDn 256

// ---------------- scratch (device globals) ----------------
__device__ __align__(16) float g_qp [Bn*HWn*Cn];
__device__ __align__(16) float g_pc [Bn*HWn*Cn];
__device__ __align__(16) float g_xi [Bn*NHn*HWn*Cn];
__device__ __align__(16) float g_cat[(size_t)Bn*NHn*HWn*96];

__device__ __align__(16) float g_b1 [NHn*96];
__device__ __align__(16) float g_b2 [NHn*64];
__device__ __align__(16) float g_b3k[NHn*32];
__device__ __align__(16) float g_wc [NHn*96*32];
__device__ __align__(16) float g_bc [NHn*32];
__device__ __align__(16) float g_wv [CDn*Cn];
__device__ __align__(16) float g_wvb[Cn];

// mma B-fragment-ordered bf16 weights (packed ushort pairs in uint32)
// layout index = ((((h*9 + tap)*NB + nb)*2 + kb)*2 + hl)*64 + lane*2 + r
__device__ __align__(16) uint32_t g_Wf1[NHn*9*12*2*2*64];  // 221184
__device__ __align__(16) uint32_t g_Wf2[NHn*9* 8*2*2*64];  // 147456
__device__ __align__(16) uint32_t g_Wf3[NHn*9* 4*2*2*64];  //  73728

// ---------------- helpers ----------------
__device__ __forceinline__ float4 f4fma(float a, float4 w, float4 acc) {
    acc.x = fmaf(a, w.x, acc.x); acc.y = fmaf(a, w.y, acc.y);
    acc.z = fmaf(a, w.z, acc.z); acc.w = fmaf(a, w.w, acc.w);
    return acc;
}
__device__ __forceinline__ uint32_t smem_u32(const void* p) {
    uint32_t a;
    asm("{ .reg .u64 t; cvta.to.shared.u64 t, %1; cvt.u32.u64 %0, t; }" : "=r"(a) : "l"(p));
    return a;
}
__device__ __forceinline__ void ldm4(uint32_t* r, uint32_t addr) {
    asm volatile("ldmatrix.sync.aligned.m8n8.x4.shared.b16 {%0,%1,%2,%3}, [%4];"
        : "=r"(r[0]), "=r"(r[1]), "=r"(r[2]), "=r"(r[3]) : "r"(addr));
}
__device__ __forceinline__ void mma4(float* d, const uint32_t* a, uint32_t b0, uint32_t b1) {
    asm volatile(
        "mma.sync.aligned.m16n8k16.row.col.f32.bf16.bf16.f32 "
        "{%0,%1,%2,%3}, {%4,%5,%6,%7}, {%8,%9}, {%0,%1,%2,%3};"
        : "+f"(d[0]), "+f"(d[1]), "+f"(d[2]), "+f"(d[3])
        : "r"(a[0]), "r"(a[1]), "r"(a[2]), "r"(a[3]), "r"(b0), "r"(b1));
}

// ---------------- prep: fold scales (1x1 weights, biases) ----------------
__global__ void prep_kernel(const float* __restrict__ wv_w, const float* __restrict__ wv_s,
                            const float* __restrict__ wv_b, const float* __restrict__ b3,
                            const float* __restrict__ wcat, const float* __restrict__ scat,
                            const float* __restrict__ bcat)
{
    int t = blockIdx.x * blockDim.x + threadIdx.x;
    const int NC = NHn*96*Cn, NV = CDn*Cn;
    if (t < NC) {
        int co = t & 31; int r = t >> 5; int ci = r % 96; int h = r / 96;
        g_wc[t] = wcat[(h*32 + co)*96 + ci] * scat[h*32 + co]; return;
    } t -= NC;
    if (t < NV) {
        int co = t & 31; int ci = t >> 5;
        g_wv[t] = wv_w[co*CDn + ci] * wv_s[co]; return;
    } t -= NV;
    if (t < NHn*96) {
        int co = t % 96; int h = t / 96; int j = co >> 5, oc = co & 31;
        g_b1[t] = b3[(h*6 + j)*32 + oc]; return;
    } t -= NHn*96;
    if (t < NHn*64) {
        int co = t % 64; int h = t / 64; int j = 3 + (co >> 5), oc = co & 31;
        g_b2[t] = b3[(h*6 + j)*32 + oc]; return;
    } t -= NHn*64;
    if (t < NHn*32) { int oc = t & 31; int h = t >> 5; g_b3k[t] = b3[(h*6 + 5)*32 + oc]; return; }
    t -= NHn*32;
    if (t < NHn*32) { g_bc[t] = bcat[t]; return; }
    t -= NHn*32;
    if (t < Cn) g_wvb[t] = wv_b[t];
}

// ---------------- prep: mma-fragment-ordered bf16 hi/lo conv weights ----------------
__global__ void prepB_kernel(const float* __restrict__ w3, const float* __restrict__ s3)
{
    const int C1 = NHn*9*12*256, C2 = NHn*9*8*256, C3 = NHn*9*4*256;
    int t = blockIdx.x * blockDim.x + threadIdx.x;
    uint32_t* dst; int NB, jb, idx;
    if (t < C1)              { dst = g_Wf1; NB = 12; jb = 0; idx = t; }
    else if ((t -= C1) < C2) { dst = g_Wf2; NB = 8;  jb = 3; idx = t; }
    else if ((t -= C2) < C3) { dst = g_Wf3; NB = 4;  jb = 5; idx = t; }
    else return;
    int r    = idx & 1;
    int lane = (idx >> 1) & 31;
    int hl   = (idx >> 6) & 1;
    int kb   = (idx >> 7) & 1;
    int nb   = (idx >> 8) % NB;
    int rest = (idx >> 8) / NB;
    int tap  = rest % 9;
    int h    = rest / 9;
    int n  = nb*8 + (lane >> 2);
    int j  = jb + (n >> 5);
    int oc = n & 31;
    int ci0 = kb*16 + (lane & 3)*2 + r*8;
    int ky = tap / 3, kx = tap % 3;
    float s = s3[(h*6 + j)*32 + oc];
    float w0 = w3[((((h*6 + j)*32 + oc)*32 + ci0    )*3 + ky)*3 + kx] * s;
    float w1 = w3[((((h*6 + j)*32 + oc)*32 + ci0 + 1)*3 + ky)*3 + kx] * s;
    __nv_bfloat16 h0 = __float2bfloat16(w0), h1 = __float2bfloat16(w1);
    unsigned short u0, u1;
    if (hl == 0) { u0 = __bfloat16_as_ushort(h0); u1 = __bfloat16_as_ushort(h1); }
    else {
        u0 = __bfloat16_as_ushort(__float2bfloat16(w0 - __bfloat162float(h0)));
        u1 = __bfloat16_as_ushort(__float2bfloat16(w1 - __bfloat162float(h1)));
    }
    dst[idx] = (uint32_t)u0 | ((uint32_t)u1 << 16);
}

// ---------------- qp = relu(conv1x1(res)+b), NCHW -> NHWC ----------------
__global__ void __launch_bounds__(128) qp_kernel(const float* __restrict__ res)
{
    __shared__ __align__(16) float sw[CDn*Cn];
    __shared__ float sb[Cn];
    for (int i = threadIdx.x; i < CDn*Cn; i += 128) sw[i] = g_wv[i];
    if (threadIdx.x < Cn) sb[threadIdx.x] = g_wvb[threadIdx.x];
    __syncthreads();
    int p0 = blockIdx.x * 256 + threadIdx.x;
    int b  = p0 >> 14;  int pix0 = p0 & 16383;
    const float* r0 = res + (size_t)b * CDn * HWn + pix0;
    float4 a0[8], a1[8];
    #pragma unroll
    for (int j = 0; j < 8; j++) { a0[j] = make_float4(0,0,0,0); a1[j] = make_float4(0,0,0,0); }
    for (int ci = 0; ci < CDn; ci++) {
        float x0 = r0[(size_t)ci * HWn], x1 = r0[(size_t)ci * HWn + 128];
        const float4* wr = (const float4*)(sw + ci*Cn);
        #pragma unroll
        for (int j = 0; j < 8; j++) { float4 w = wr[j]; a0[j] = f4fma(x0, w, a0[j]); a1[j] = f4fma(x1, w, a1[j]); }
    }
    float4* o0 = (float4*)(g_qp + (size_t)p0 * Cn);
    float4* o1 = (float4*)(g_qp + (size_t)(p0 + 128) * Cn);
    #pragma unroll
    for (int j = 0; j < 8; j++) {
        float4 v0 = a0[j], v1 = a1[j];
        v0.x = fmaxf(v0.x + sb[j*4+0], 0.f); v0.y = fmaxf(v0.y + sb[j*4+1], 0.f);
        v0.z = fmaxf(v0.z + sb[j*4+2], 0.f); v0.w = fmaxf(v0.w + sb[j*4+3], 0.f);
        v1.x = fmaxf(v1.x + sb[j*4+0], 0.f); v1.y = fmaxf(v1.y + sb[j*4+1], 0.f);
        v1.z = fmaxf(v1.z + sb[j*4+2], 0.f); v1.w = fmaxf(v1.w + sb[j*4+3], 0.f);
        o0[j] = v0; o1[j] = v1;
    }
}

// ---------------- point attention ----------------
__global__ void __launch_bounds__(256) pa_kernel()
{
    int p = blockIdx.x * 256 + threadIdx.x;
    int b = p >> 14, pix = p & 16383, h = pix >> 7, w = pix & 127;
    const float4* q4 = (const float4*)g_qp + (size_t)p * 8;
    float4 q[8];
    #pragma unroll
    for (int j = 0; j < 8; j++) q[j] = q4[j];
    float sc[25];
    #pragma unroll
    for (int k = 0; k < 25; k++) {
        int di = (k / 5) * 2 - 4, dj = (k % 5) * 2 - 4;
        int hh = h + di, ww = w + dj;
        float s = 0.f;
        if (k != 12 && hh >= 0 && hh < Hn && ww >= 0 && ww < Wn) {
            const float4* nb = (const float4*)g_qp + (size_t)((b << 14) + (hh << 7) + ww) * 8;
            #pragma unroll
            for (int j = 0; j < 8; j++) { float4 v = nb[j]; s += q[j].x*v.x + q[j].y*v.y + q[j].z*v.z + q[j].w*v.w; }
        }
        sc[k] = s;
    }
    float m = sc[0];
    #pragma unroll
    for (int k = 1; k < 25; k++) m = fmaxf(m, sc[k]);
    float Z = 0.f;
    #pragma unroll
    for (int k = 0; k < 25; k++) { sc[k] = __expf(sc[k] - m); Z += sc[k]; }
    float inv = 1.f / Z;
    float4 acc[8];
    #pragma unroll
    for (int j = 0; j < 8; j++) acc[j] = q[j];
    #pragma unroll
    for (int k = 0; k < 25; k++) {
        int di = (k / 5) * 2 - 4, dj = (k % 5) * 2 - 4;
        int hh = h + di, ww = w + dj;
        if (hh >= 0 && hh < Hn && ww >= 0 && ww < Wn) {
            float wgt = sc[k] * inv;
            const float4* nb = (const float4*)g_qp + (size_t)((b << 14) + (hh << 7) + ww) * 8;
            #pragma unroll
            for (int j = 0; j < 8; j++) acc[j] = f4fma(wgt, nb[j], acc[j]);
        }
    }
    float4* o = (float4*)(g_pc + (size_t)p * Cn);
    #pragma unroll
    for (int j = 0; j < 8; j++) o[j] = acc[j];
}

// ---------------- class attention + norm + residual -> xi ----------------
__global__ void __launch_bounds__(256) ca_kernel(const float* __restrict__ attn,
                                                 const float* __restrict__ cn_s,
                                                 const float* __restrict__ cn_b)
{
    int p = blockIdx.x * 256 + threadIdx.x;
    int b = p >> 14, pix = p & 16383;
    float pcf[32];
    const float4* pc4 = (const float4*)g_pc + (size_t)p * 8;
    #pragma unroll
    for (int j = 0; j < 8; j++) {
        float4 v = pc4[j];
        pcf[j*4+0] = v.x; pcf[j*4+1] = v.y; pcf[j*4+2] = v.z; pcf[j*4+3] = v.w;
    }
    float s[8];
    #pragma unroll
    for (int n = 0; n < 8; n++) {
        const float* ap = attn + ((size_t)b * CDn + n * Cn) * HWn + pix;
        float acc = 0.f;
        #pragma unroll
        for (int c = 0; c < 32; c++) acc += pcf[c] * ap[(size_t)c * HWn];
        s[n] = acc;
    }
    float m = s[0];
    #pragma unroll
    for (int n = 1; n < 8; n++) m = fmaxf(m, s[n]);
    float Z = 0.f;
    #pragma unroll
    for (int n = 0; n < 8; n++) { s[n] = __expf(s[n] - m); Z += s[n]; }
    float inv = 1.f / Z;
    #pragma unroll
    for (int n = 0; n < 8; n++) {
        float wn = s[n] * inv;
        const float* ap = attn + ((size_t)b * CDn + n * Cn) * HWn + pix;
        float4* xo = (float4*)(g_xi + ((size_t)(b * NHn + n) * HWn + pix) * Cn);
        #pragma unroll
        for (int c4 = 0; c4 < 8; c4++) {
            float4 o; int c = c4 * 4;
            o.x = ap[(size_t)(c+0)*HWn] + wn * pcf[c+0] * __ldg(&cn_s[n*32+c+0]) + __ldg(&cn_b[n*32+c+0]);
            o.y = ap[(size_t)(c+1)*HWn] + wn * pcf[c+1] * __ldg(&cn_s[n*32+c+1]) + __ldg(&cn_b[n*32+c+1]);
            o.z = ap[(size_t)(c+2)*HWn] + wn * pcf[c+2] * __ldg(&cn_s[n*32+c+2]) + __ldg(&cn_b[n*32+c+2]);
            o.w = ap[(size_t)(c+3)*HWn] + wn * pcf[c+3] * __ldg(&cn_s[n*32+c+3]) + __ldg(&cn_b[n*32+c+3]);
            xo[c4] = o;
        }
    }
}

// ---------------- MSConv 3x3 stage via warp MMA (bf16 hi/lo, f32 accum) ----------------
// S=1: in g_xi (32ch)        -> 3 branches -> relu6 group-sum -> g_cat[0:32)
// S=2: in g_cat[0:32)        -> 2 branches -> relu6 group-sum -> g_cat[32:64)
// S=3: in g_cat[32:64)       -> 1 branch   -> relu6           -> g_cat[64:96)
// smem: hi plane [324 rows x 80B] @0, lo plane @25920, W frags @51840, bias after.
template <int S>
__global__ void __launch_bounds__(256) conv_mma_kernel()
{
    constexpr int NBW = (S == 1) ? 3 : (S == 2) ? 2 : 1;
    constexpr int NB  = NBW * 4;
    constexpr int WCNT = 9 * NB * 256;          // uint32 per head
    constexpr int WBYTES = WCNT * 4;
    constexpr int INS  = (S == 1) ? 32 : 96;
    constexpr int CHOFF = (S == 3) ? 32 : 0;
    constexpr int OUTOFF = (S == 1) ? 0 : (S == 2) ? 32 : 64;

    extern __shared__ __align__(16) char smem[];
    const int tid = threadIdx.x;
    const int img = blockIdx.y, head = img & 7;
    const int ty0 = (blockIdx.x >> 3) * 16, tx0 = (blockIdx.x & 7) * 16;

    // ---- load weights (fragment-ordered) + bias ----
    {
        const uint32_t* gWf = (S == 1) ? g_Wf1 : (S == 2) ? g_Wf2 : g_Wf3;
        const uint4* wsrc = (const uint4*)(gWf + (size_t)head * WCNT);
        uint4* wdst = (uint4*)(smem + 51840);
        for (int i = tid; i < WCNT / 4; i += 256) wdst[i] = wsrc[i];
        const float* gB = (S == 1) ? g_b1 : (S == 2) ? g_b2 : g_b3k;
        float* sb = (float*)(smem + 51840 + WBYTES);
        if (tid < NB * 8) sb[tid] = gB[head * NB * 8 + tid];
    }

    // ---- build A halo planes (hi/lo bf16), rows padded to 80B ----
    {
        const float* gin = (S == 1) ? g_xi + (size_t)img * HWn * 32
                                    : g_cat + (size_t)img * HWn * 96;
        for (int e = tid; e < 324; e += 256) {
            int iy = e / 18, ix = e - iy * 18;
            int hh = ty0 - 1 + iy, ww = tx0 - 1 + ix;
            float x[32];
            if (hh >= 0 && hh < Hn && ww >= 0 && ww < Wn) {
                const float4* p = (const float4*)(gin + (size_t)(hh * Wn + ww) * INS + CHOFF);
                #pragma unroll
                for (int q = 0; q < 8; q++) {
                    float4 v = p[q];
                    x[4*q] = v.x; x[4*q+1] = v.y; x[4*q+2] = v.z; x[4*q+3] = v.w;
                }
            } else {
                #pragma unroll
                for (int i = 0; i < 32; i++) x[i] = 0.f;
            }
            uint32_t hq[16], lq[16];
            #pragma unroll
            for (int i = 0; i < 16; i++) {
                __nv_bfloat16 h0 = __float2bfloat16(x[2*i]),   h1 = __float2bfloat16(x[2*i+1]);
                __nv_bfloat16 l0 = __float2bfloat16(x[2*i]   - __bfloat162float(h0));
                __nv_bfloat16 l1 = __float2bfloat16(x[2*i+1] - __bfloat162float(h1));
                hq[i] = (uint32_t)__bfloat16_as_ushort(h0) | ((uint32_t)__bfloat16_as_ushort(h1) << 16);
                lq[i] = (uint32_t)__bfloat16_as_ushort(l0) | ((uint32_t)__bfloat16_as_ushort(l1) << 16);
            }
            uint4* rh = (uint4*)(smem + e * 80);
            uint4* rl = (uint4*)(smem + 25920 + e * 80);
            #pragma unroll
            for (int q = 0; q < 4; q++) {
                rh[q] = make_uint4(hq[4*q], hq[4*q+1], hq[4*q+2], hq[4*q+3]);
                rl[q] = make_uint4(lq[4*q], lq[4*q+1], lq[4*q+2], lq[4*q+3]);
            }
        }
    }
    __syncthreads();

    // ---- warp MMA mainloop ----
    const int lane = tid & 31, wid = tid >> 5;
    const int warpM = wid & 1, warpN = wid >> 1;
    const int mloc = lane & 15;
    const uint32_t koff = (lane & 16) ? 16u : 0u;
    const uint32_t abase = smem_u32(smem) + (uint32_t)mloc * 80 + koff;
    const uint2* wf = (const uint2*)(smem + 51840);
    const float* sbias = (const float*)(smem + 51840 + WBYTES);

    float acc[8][NBW][4];
    #pragma unroll
    for (int mb = 0; mb < 8; mb++)
        #pragma unroll
        for (int g = 0; g < NBW; g++)
            #pragma unroll
            for (int c = 0; c < 4; c++) acc[mb][g][c] = 0.f;

    #pragma unroll 1
    for (int tap = 0; tap < 9; tap++) {
        const int ky = tap / 3, kx = tap - ky * 3;
        uint32_t bh[NBW][4], bl[NBW][4];
        #pragma unroll
        for (int g = 0; g < NBW; g++) {
            int nb = warpN + g * 4;
            #pragma unroll
            for (int kb = 0; kb < 2; kb++) {
                uint2 vh = wf[(size_t)((((tap * NB + nb) * 2 + kb) * 2 + 0) * 32 + lane)];
                uint2 vl = wf[(size_t)((((tap * NB + nb) * 2 + kb) * 2 + 1) * 32 + lane)];
                bh[g][2*kb] = vh.x; bh[g][2*kb+1] = vh.y;
                bl[g][2*kb] = vl.x; bl[g][2*kb+1] = vl.y;
            }
        }
        const uint32_t rowbase = abase + (uint32_t)(((warpM * 8 + ky) * 18 + kx) * 80);
        #pragma unroll
        for (int mb = 0; mb < 8; mb++) {
            uint32_t ab = rowbase + (uint32_t)(mb * 18 * 80);
            uint32_t ah0[4], ah1[4], al0[4], al1[4];
            ldm4(ah0, ab);           ldm4(ah1, ab + 32);
            ldm4(al0, ab + 25920);   ldm4(al1, ab + 25920 + 32);
            #pragma unroll
            for (int g = 0; g < NBW; g++) {
                mma4(acc[mb][g], ah0, bh[g][0], bh[g][1]);
                mma4(acc[mb][g], ah1, bh[g][2], bh[g][3]);
                mma4(acc[mb][g], al0, bh[g][0], bh[g][1]);
                mma4(acc[mb][g], al1, bh[g][2], bh[g][3]);
                mma4(acc[mb][g], ah0, bl[g][0], bl[g][1]);
                mma4(acc[mb][g], ah1, bl[g][2], bl[g][3]);
            }
        }
    }

    // ---- epilogue: bias + relu6 + thread-local group sum -> g_cat ----
    const int nl = (lane & 3) * 2;
    #pragma unroll
    for (int mb = 0; mb < 8; mb++) {
        int py = ty0 + warpM * 8 + mb;
        float o[4];
        #pragma unroll
        for (int c = 0; c < 4; c++) {
            float s = 0.f;
            #pragma unroll
            for (int g = 0; g < NBW; g++) {
                float b = sbias[(warpN + g * 4) * 8 + nl + (c & 1)];
                s += fminf(fmaxf(acc[mb][g][c] + b, 0.f), 6.f);
            }
            o[c] = s;
        }
        int pxg = tx0 + (lane >> 2);
        int ch = OUTOFF + warpN * 8 + nl;
        float* p0 = g_cat + ((size_t)img * HWn + (size_t)py * Wn + pxg) * 96 + ch;
        *(float2*)p0 = make_float2(o[0], o[1]);
        *(float2*)(p0 + 8 * 96) = make_float2(o[2], o[3]);
    }
}

// ---------------- 1x1 conv 96->32 + bias + residual(xi) + relu -> NCHW out ----------------
__global__ void __launch_bounds__(256) final_kernel(float* __restrict__ out)
{
    __shared__ __align__(16) float sw[96 * 32];
    __shared__ float sb[32];
    const int img = blockIdx.y, head = img & 7;
    const float* gw = g_wc + (size_t)head * 96 * 32;
    for (int i = threadIdx.x; i < 96 * 32; i += 256) sw[i] = gw[i];
    if (threadIdx.x < 32) sb[threadIdx.x] = g_bc[head * 32 + threadIdx.x];
    __syncthreads();
    const int p = blockIdx.x * 256 + threadIdx.x;
    const float4* cv = (const float4*)(g_cat + ((size_t)img * HWn + p) * 96);
    float4 acc[8];
    #pragma unroll
    for (int j = 0; j < 8; j++) acc[j] = make_float4(0, 0, 0, 0);
    #pragma unroll 1
    for (int ci4 = 0; ci4 < 24; ci4++) {
        float4 xv = cv[ci4];
        const float4* w0 = (const float4*)(sw + (ci4 * 4 + 0) * 32);
        const float4* w1 = (const float4*)(sw + (ci4 * 4 + 1) * 32);
        const float4* w2 = (const float4*)(sw + (ci4 * 4 + 2) * 32);
        const float4* w3p = (const float4*)(sw + (ci4 * 4 + 3) * 32);
        #pragma unroll
        for (int j = 0; j < 8; j++) {
            acc[j] = f4fma(xv.x, w0[j], acc[j]);
            acc[j] = f4fma(xv.y, w1[j], acc[j]);
            acc[j] = f4fma(xv.z, w2[j], acc[j]);
            acc[j] = f4fma(xv.w, w3p[j], acc[j]);
        }
    }
    const float4* xiv = (const float4*)(g_xi + ((size_t)img * HWn + p) * Cn);
    #pragma unroll
    for (int j = 0; j < 8; j++) {
        float4 xr = xiv[j];
        float ox = fmaxf(acc[j].x + sb[j*4+0] + xr.x, 0.f);
        float oy = fmaxf(acc[j].y + sb[j*4+1] + xr.y, 0.f);
        float oz = fmaxf(acc[j].z + sb[j*4+2] + xr.z, 0.f);
        float ow = fmaxf(acc[j].w + sb[j*4+3] + xr.w, 0.f);
        size_t base = (size_t)(img * 32 + j * 4) * HWn + p;
        out[base] = ox; out[base + HWn] = oy; out[base + 2*HWn] = oz; out[base + 3*HWn] = ow;
    }
}

// ---------------- launch ----------------
extern "C" void kernel_launch(void* const* d_in, const int* in_sizes, int n_in,
                              void* d_out, int out_size)
{
    (void)in_sizes; (void)n_in; (void)out_size;
    const float* res  = (const float*)d_in[0];
    const float* attn = (const float*)d_in[1];
    const float* wv_w = (const float*)d_in[2];
    const float* wv_s = (const float*)d_in[3];
    const float* wv_b = (const float*)d_in[4];
    const float* cn_s = (const float*)d_in[5];
    const float* cn_b = (const float*)d_in[6];
    const float* w3   = (const float*)d_in[7];
    const float* s3   = (const float*)d_in[8];
    const float* b3   = (const float*)d_in[9];
    const float* wcat = (const float*)d_in[10];
    const float* scat = (const float*)d_in[11];
    const float* bcat = (const float*)d_in[12];
    float* out = (float*)d_out;

    const int SM1 = 51840 + 9*12*256*4 + 12*8*4;   // 162816 + 384
    const int SM2 = 51840 + 9*8*256*4  + 8*8*4;    // 125568 + 256
    const int SM3 = 51840 + 9*4*256*4  + 4*8*4;    //  88704 + 128
    cudaFuncSetAttribute(conv_mma_kernel<1>, cudaFuncAttributeMaxDynamicSharedMemorySize, SM1);
    cudaFuncSetAttribute(conv_mma_kernel<2>, cudaFuncAttributeMaxDynamicSharedMemorySize, SM2);
    cudaFuncSetAttribute(conv_mma_kernel<3>, cudaFuncAttributeMaxDynamicSharedMemorySize, SM3);

    prep_kernel<<<140, 256>>>(wv_w, wv_s, wv_b, b3, wcat, scat, bcat);
    prepB_kernel<<<1728, 256>>>(w3, s3);
    qp_kernel<<<256, 128>>>(res);
    pa_kernel<<<256, 256>>>();
    ca_kernel<<<256, 256>>>(attn, cn_s, cn_b);
    conv_mma_kernel<1><<<dim3(64, 32), 256, SM1>>>();
    conv_mma_kernel<2><<<dim3(64, 32), 256, SM2>>>();
    conv_mma_kernel<3><<<dim3(64, 32), 256, SM3>>>();
    final_kernel<<<dim3(64, 32), 256>>>(out);
}